// round 17
// baseline (speedup 1.0000x reference)
#include <cuda_runtime.h>
#include <cuda_fp16.h>
#include <cstdint>

#define IN 784
#define HIDN 64
#define KTOP 20
#define NCH 49                // 49 chunks of 16 k (784 = 49*16)
#define GRP 7                 // chunks per weight group
#define NGRP 7                // 49 / 7
#define KCH_D 4               // decoder k16-chunks (64 = 4*16)
#define NPAD 832
#define EPS_GAP 1e-4f

// Pre-split fp16 weights in B-fragment layout with COLUMN PERMUTATION:
// fragment (tile t, tile-col j) maps to global col (j>>1)*16 + 2t + (j&1),
// so each C-fragment thread owns 16 CONTIGUOUS global columns -> STG.128
// epilogue. Per (k16-chunk, fragcol, tg): uint4 = (bh0, bh1, bl0, bl1).
__device__ uint4 g_Be[NCH * 64 * 4];          // 200 KB
__device__ uint4 g_Bd[KCH_D * NPAD * 4];      // 212 KB

// ---- fp16 split helpers ----
__device__ __forceinline__ void spl16(float a, float b, unsigned &hi, unsigned &lo) {
    __half2 h = __floats2half2_rn(a, b);
    float ra = a - __low2float(h);
    float rb = b - __high2float(h);
    __half2 l = __floats2half2_rn(ra, rb);
    hi = reinterpret_cast<unsigned&>(h);
    lo = reinterpret_cast<unsigned&>(l);
}
__device__ __forceinline__ void mmaf16(float* c, const unsigned* a, unsigned b0, unsigned b1) {
    asm volatile(
        "mma.sync.aligned.m16n8k16.row.col.f32.f16.f16.f32 "
        "{%0,%1,%2,%3},{%4,%5,%6,%7},{%8,%9},{%0,%1,%2,%3};"
        : "+f"(c[0]), "+f"(c[1]), "+f"(c[2]), "+f"(c[3])
        : "r"(a[0]), "r"(a[1]), "r"(a[2]), "r"(a[3]), "r"(b0), "r"(b1));
}
__device__ __forceinline__ void mma3h(float* c, const unsigned* ah, const unsigned* al, uint4 bv) {
    mmaf16(c, ah, bv.x, bv.y);
    mmaf16(c, al, bv.x, bv.y);
    mmaf16(c, ah, bv.z, bv.w);
}
// ---- cp.async ----
__device__ __forceinline__ void cp16(void* sdst, const void* gsrc) {
    unsigned sa = (unsigned)__cvta_generic_to_shared(sdst);
    asm volatile("cp.async.ca.shared.global [%0], [%1], 16;" :: "r"(sa), "l"(gsrc));
}
#define CP_COMMIT() asm volatile("cp.async.commit_group;")
#define CP_WAIT0()  asm volatile("cp.async.wait_group 0;" ::: "memory")

// fragment flat col (0..63) -> permuted col within the 64-wide tile
__device__ __forceinline__ int permcol(int flat) {
    int t = flat >> 3, j = flat & 7;
    return ((j >> 1) << 4) + 2 * t + (j & 1);
}

// ---------------- K0: split weights to fp16 hi/lo fragment layout ----------
__global__ void k_prep(const float* __restrict__ We, const float* __restrict__ Wd) {
    int idx = blockIdx.x * 256 + threadIdx.x;
    const int NE = NCH * 64 * 4;                  // 12544
    if (idx < NE) {
        int kc = idx >> 8, r = idx & 255, n = r >> 2, tg = r & 3;
        int gcol = permcol(n);                    // HIDN tile is a single block
        int k0 = kc * 16 + 2 * tg;
        float w0 = We[gcol * IN + k0],     w1 = We[gcol * IN + k0 + 1];
        float w2 = We[gcol * IN + k0 + 8], w3 = We[gcol * IN + k0 + 9];
        uint4 v;
        spl16(w0, w1, v.x, v.z);
        spl16(w2, w3, v.y, v.w);
        g_Be[idx] = v;
    }
    int j = idx - NE;
    const int ND = KCH_D * NPAD * 4;              // 13312
    if (j >= 0 && j < ND) {
        int kc = j / (NPAD * 4), r = j % (NPAD * 4), n = r >> 2, tg = r & 3;
        int gcol = (n & ~63) + permcol(n & 63);   // permute within 64-col block
        int k0 = kc * 16 + 2 * tg;
        float w0 = 0.f, w1 = 0.f, w2 = 0.f, w3 = 0.f;
        if (gcol < IN) {
            w0 = Wd[gcol * HIDN + k0];     w1 = Wd[gcol * HIDN + k0 + 1];
            w2 = Wd[gcol * HIDN + k0 + 8]; w3 = Wd[gcol * HIDN + k0 + 9];
        }
        uint4 v;
        spl16(w0, w1, v.x, v.z);
        spl16(w2, w3, v.y, v.w);
        g_Bd[j] = v;
    }
}

// ---------------- K1: encoder GEMM (3xFP16 m16n8k16) + bias + ReLU ---------
// CTA = 256 rows x 64 cols, 8 warps, warp = 32 rows. x direct from global;
// weights paged in groups of 7 chunks (28KB, 2 slots). STG.128 epilogue via
// column permutation: thread (g,tg) owns h cols [16tg, 16tg+16).
__global__ __launch_bounds__(256, 2) void k_enc(const float* __restrict__ x,
        const float* __restrict__ benc, float* __restrict__ hout, int B) {
    extern __shared__ char dyn[];
    const int tid = threadIdx.x, lane = tid & 31, w = tid >> 5;
    const int g = lane >> 2, tg = lane & 3;
    const int r0 = blockIdx.x * 256;
    const int rowb = r0 + w * 32 + g;
    const float* xp[4];
    #pragma unroll
    for (int j = 0; j < 4; j++) {
        int r = min(rowb + 8 * j, B - 1);
        xp[j] = x + (size_t)r * IN + 2 * tg;
    }

    float acc[8][8];
    #pragma unroll
    for (int t = 0; t < 8; t++)
        #pragma unroll
        for (int i = 0; i < 8; i++) acc[t][i] = 0.f;

    #pragma unroll
    for (int i = 0; i < GRP; i++) {
        int f = tid + i * 256;
        cp16(dyn + f * 16, (const char*)g_Be + f * 16);
    }
    CP_COMMIT();

    for (int gr = 0; gr < NGRP; gr++) {
        CP_WAIT0();
        __syncthreads();

        if (gr + 1 < NGRP) {
            char* sb = dyn + ((gr + 1) & 1) * 28672;
            const char* src = (const char*)g_Be + (gr + 1) * 28672;
            #pragma unroll
            for (int i = 0; i < GRP; i++) {
                int f = tid + i * 256;
                cp16(sb + f * 16, src + f * 16);
            }
            CP_COMMIT();
        }

        const char* wsb = dyn + (gr & 1) * 28672;
        #pragma unroll
        for (int lc = 0; lc < GRP; lc++) {
            const int kc = gr * GRP + lc;
            const uint4* wsp = (const uint4*)(wsb + lc * 4096);
            unsigned ah0[4], al0[4], ah1[4], al1[4];
            #pragma unroll
            for (int j = 0; j < 4; j++) {
                float2 pA = *(const float2*)(xp[j] + kc * 16);
                float2 pB = *(const float2*)(xp[j] + kc * 16 + 8);
                unsigned hA, lA, hB, lB;
                spl16(pA.x, pA.y, hA, lA);
                spl16(pB.x, pB.y, hB, lB);
                if (j < 2) { ah0[j] = hA; ah0[j + 2] = hB; al0[j] = lA; al0[j + 2] = lB; }
                else       { ah1[j - 2] = hA; ah1[j] = hB; al1[j - 2] = lA; al1[j] = lB; }
            }
            #pragma unroll
            for (int t = 0; t < 8; t++) {
                uint4 bv = wsp[(t * 8 + g) * 4 + tg];
                mma3h(acc[t],     ah0, al0, bv);
                mma3h(acc[t] + 4, ah1, al1, bv);
            }
        }
    }

    // STG.128 epilogue: thread owns cols 16tg..16tg+15; col 16tg+2t+c <- acc[t][..c]
    float bias[16];
    #pragma unroll
    for (int q = 0; q < 4; q++)
        *(float4*)(bias + 4 * q) = *(const float4*)(benc + tg * 16 + 4 * q);
    #pragma unroll
    for (int s = 0; s < 4; s++) {
        int r = rowb + 8 * s;
        if (r < B) {
            float* dst = hout + (size_t)r * HIDN + tg * 16;
            #pragma unroll
            for (int q = 0; q < 4; q++) {
                float o[4];
                #pragma unroll
                for (int e = 0; e < 4; e++) {
                    int fi = 4 * q + e, t = fi >> 1, c = fi & 1;
                    float v = acc[t][(s >> 1) * 4 + ((s & 1) << 1) + c] + bias[fi];
                    o[e] = fmaxf(v, 0.f);
                }
                *(float4*)(dst + 4 * q) = make_float4(o[0], o[1], o[2], o[3]);
            }
        }
    }
}

// ---------------- K2: top-20 gating (32-bit keys) + inline exact repair -----
__global__ __launch_bounds__(256) void k_topk(const float* __restrict__ x,
        const float* __restrict__ We, const float* __restrict__ benc,
        float* __restrict__ h, int B) {
    int warp = threadIdx.x >> 5, lane = threadIdx.x & 31;
    int row = blockIdx.x * 8 + warp;
    if (row >= B) return;
    float* hr = h + (size_t)row * HIDN;
    float v0 = hr[lane], v1 = hr[lane + 32];

    unsigned q0 = (__float_as_uint(v0) & ~63u) | (unsigned)(63 - lane);
    unsigned q1 = (__float_as_uint(v1) & ~63u) | (unsigned)(31 - lane);
    float thr = 0.f, nxt = 0.f;
    #pragma unroll
    for (int it = 0; it < KTOP + 1; it++) {
        unsigned m = (q0 > q1) ? q0 : q1;
        #pragma unroll
        for (int off = 16; off > 0; off >>= 1) {
            unsigned o = __shfl_xor_sync(0xffffffffu, m, off);
            if (o > m) m = o;
        }
        if (it == KTOP - 1) thr = __uint_as_float(m & ~63u);
        if (it == KTOP)     nxt = __uint_as_float(m & ~63u);
        if (q0 == m) q0 = 0u; else if (q1 == m) q1 = 0u;
    }

    if (thr - nxt >= EPS_GAP) {
        hr[lane]      = (v0 >= thr) ? v0 : 0.f;
        hr[lane + 32] = (v1 >= thr) ? v1 : 0.f;
        return;
    }

    // Fragile: exact fp32 recompute + exact 64-bit-key top-k.
    const float* xr = x + (size_t)row * IN;
    const float* wa = We + (size_t)lane * IN;
    const float* wb = We + (size_t)(lane + 32) * IN;
    float a0 = 0.f, a1 = 0.f;
    for (int k = 0; k < IN; k += 4) {
        float4 xv = *(const float4*)(xr + k);
        float4 va = *(const float4*)(wa + k);
        float4 vb = *(const float4*)(wb + k);
        a0 += xv.x*va.x + xv.y*va.y + xv.z*va.z + xv.w*va.w;
        a1 += xv.x*vb.x + xv.y*vb.y + xv.z*vb.z + xv.w*vb.w;
    }
    v0 = fmaxf(a0 + benc[lane], 0.f);
    v1 = fmaxf(a1 + benc[lane + 32], 0.f);
    unsigned long long k0 = ((unsigned long long)__float_as_uint(v0) << 32) | (unsigned)(63 - lane);
    unsigned long long k1 = ((unsigned long long)__float_as_uint(v1) << 32) | (unsigned)(31 - lane);
    float thx = 0.f;
    #pragma unroll
    for (int it = 0; it < KTOP; it++) {
        unsigned long long m = (k0 > k1) ? k0 : k1;
        #pragma unroll
        for (int off = 16; off > 0; off >>= 1) {
            unsigned long long o = __shfl_xor_sync(0xffffffffu, m, off);
            if (o > m) m = o;
        }
        if (it == KTOP - 1) thx = __uint_as_float((unsigned)(m >> 32));
        if (k0 == m) k0 = 0ull; else if (k1 == m) k1 = 0ull;
    }
    hr[lane]      = (v0 >= thx) ? v0 : 0.f;
    hr[lane + 32] = (v1 >= thx) ? v1 : 0.f;
}

// ---------------- K3: decoder GEMM (3xFP16 m16n8k16) + bias ----------------
// Grid (13, rowtiles). STG.128 epilogue via column permutation: thread (g,tg)
// owns x_hat cols n0+16tg .. +15.
__global__ __launch_bounds__(256, 2) void k_dec(const float* __restrict__ h,
        const float* __restrict__ bdec, float* __restrict__ xhat, int B) {
    __shared__ uint4 ws4[KCH_D * 256];            // 16 KB
    const int tid = threadIdx.x, lane = tid & 31, w = tid >> 5;
    const int g = lane >> 2, tg = lane & 3;
    const int r0 = blockIdx.y * 256;
    const int n0 = blockIdx.x * 64;
    const int rowb = r0 + w * 32 + g;
    const float* hp[4];
    #pragma unroll
    for (int j = 0; j < 4; j++) {
        int r = min(rowb + 8 * j, B - 1);
        hp[j] = h + (size_t)r * HIDN + 2 * tg;
    }

    #pragma unroll
    for (int i = 0; i < 4; i++) {
        int f = tid + i * 256;
        int kc = f >> 8, r = f & 255, n = r >> 2, tgq = r & 3;
        cp16(&ws4[f], g_Bd + (size_t)(kc * NPAD + n0 + n) * 4 + tgq);
    }
    CP_COMMIT();
    CP_WAIT0();
    __syncthreads();

    float acc[8][8];
    #pragma unroll
    for (int t = 0; t < 8; t++)
        #pragma unroll
        for (int i = 0; i < 8; i++) acc[t][i] = 0.f;

    #pragma unroll
    for (int kc = 0; kc < KCH_D; kc++) {
        unsigned ah0[4], al0[4], ah1[4], al1[4];
        #pragma unroll
        for (int j = 0; j < 4; j++) {
            float2 pA = *(const float2*)(hp[j] + kc * 16);
            float2 pB = *(const float2*)(hp[j] + kc * 16 + 8);
            unsigned hA, lA, hB, lB;
            spl16(pA.x, pA.y, hA, lA);
            spl16(pB.x, pB.y, hB, lB);
            if (j < 2) { ah0[j] = hA; ah0[j + 2] = hB; al0[j] = lA; al0[j + 2] = lB; }
            else       { ah1[j - 2] = hA; ah1[j] = hB; al1[j - 2] = lA; al1[j] = lB; }
        }
        #pragma unroll
        for (int t = 0; t < 8; t++) {
            uint4 bv = ws4[kc * 256 + (t * 8 + g) * 4 + tg];
            mma3h(acc[t],     ah0, al0, bv);
            mma3h(acc[t] + 4, ah1, al1, bv);
        }
    }

    // STG.128 epilogue: thread owns cols n0+16tg+0..15 (col n0+16tg+2t+c)
    const int cb = n0 + tg * 16;
    float bias[16];
    #pragma unroll
    for (int q = 0; q < 4; q++) {
        if (cb + 4 * q + 3 < IN)
            *(float4*)(bias + 4 * q) = *(const float4*)(bdec + cb + 4 * q);
    }
    #pragma unroll
    for (int s = 0; s < 4; s++) {
        int r = rowb + 8 * s;
        if (r < B) {
            float* dst = xhat + (size_t)r * IN + cb;
            #pragma unroll
            for (int q = 0; q < 4; q++) {
                if (cb + 4 * q + 3 < IN) {
                    float o[4];
                    #pragma unroll
                    for (int e = 0; e < 4; e++) {
                        int fi = 4 * q + e, t = fi >> 1, c = fi & 1;
                        o[e] = acc[t][(s >> 1) * 4 + ((s & 1) << 1) + c] + bias[fi];
                    }
                    *(float4*)(dst + 4 * q) = make_float4(o[0], o[1], o[2], o[3]);
                }
            }
        }
    }
}

extern "C" void kernel_launch(void* const* d_in, const int* in_sizes, int n_in,
                              void* d_out, int out_size) {
    const float* x    = (const float*)d_in[0];
    const float* We   = (const float*)d_in[1];
    const float* benc = (const float*)d_in[2];
    const float* Wd   = (const float*)d_in[3];
    const float* bdec = (const float*)d_in[4];
    int B = in_sizes[0] / IN;

    float* hout = (float*)d_out;                         // [B, 64]
    float* xhat = (float*)d_out + (size_t)B * HIDN;      // [B, 784]

    const int SMEM_ENC = 2 * 28672;                      // 57344 bytes
    cudaFuncSetAttribute(k_enc, cudaFuncAttributeMaxDynamicSharedMemorySize, SMEM_ENC);

    const int NPREP = NCH * 64 * 4 + KCH_D * NPAD * 4;
    k_prep<<<(NPREP + 255) / 256, 256>>>(We, Wd);
    k_enc<<<(B + 255) / 256, 256, SMEM_ENC>>>(x, benc, hout, B);
    k_topk<<<(B + 7) / 8, 256>>>(x, We, benc, hout, B);
    k_dec<<<dim3(13, (B + 255) / 256), 256>>>(hout, bdec, xhat, B);
}